// round 3
// baseline (speedup 1.0000x reference)
#include <cuda_runtime.h>
#include <cstdint>

#define NE 8
#define DMODEL 1024
#define DFF 4096
#define TTOK 2048

#define BM 128
#define BN 64
#define BK 32
#define LDA 36   // 128-row A tile, padded: banks = 4*qr + qc, conflict-free
#define LDB 72   // 32-row B tile, padded: banks = 8*qc + qr, conflict-free

// Scratch (allocation-free rule: __device__ globals)
__device__ int   g_perm[TTOK];
__device__ int   g_off[NE + 1];
__device__ float g_h[(size_t)TTOK * DFF];   // gathered hidden activations

// ---------------- helpers ----------------
__device__ __forceinline__ void cp16(float* dst, const float* src, int sz) {
    uint32_t d = (uint32_t)__cvta_generic_to_shared(dst);
    asm volatile("cp.async.cg.shared.global [%0], [%1], 16, %2;\n"
                 :: "r"(d), "l"(src), "r"(sz));
}
__device__ __forceinline__ void cp_commit() {
    asm volatile("cp.async.commit_group;\n");
}
__device__ __forceinline__ uint32_t f2tf(float f) {
    uint32_t u;
    asm("cvt.rna.tf32.f32 %0, %1;\n" : "=r"(u) : "f"(f));
    return u;
}
__device__ __forceinline__ void mma8(float c[4], const uint32_t a[4], const uint32_t b[2]) {
    asm volatile(
        "mma.sync.aligned.m16n8k8.row.col.f32.tf32.tf32.f32 "
        "{%0,%1,%2,%3}, {%4,%5,%6,%7}, {%8,%9}, {%0,%1,%2,%3};\n"
        : "+f"(c[0]), "+f"(c[1]), "+f"(c[2]), "+f"(c[3])
        : "r"(a[0]), "r"(a[1]), "r"(a[2]), "r"(a[3]), "r"(b[0]), "r"(b[1]));
}

// ---------------- kernel 1: bucket tokens by expert ----------------
__global__ void moe_build_perm(const void* eidx_raw) {
    __shared__ int cnt[NE], base[NE], nz;
    int t = threadIdx.x;
    if (t < NE) cnt[t] = 0;
    if (t == 0) nz = 0;
    __syncthreads();

    // dtype detection: int64 data has all-zero high words; int32 random expert
    // ids at odd token positions are ~never all zero.
    const int* i32 = (const int*)eidx_raw;
    for (int i = t; i < TTOK / 2; i += blockDim.x)
        if (i32[2 * i + 1] != 0) atomicOr(&nz, 1);
    __syncthreads();
    bool is64 = (nz == 0);
    const long long* i64 = (const long long*)eidx_raw;

    for (int i = t; i < TTOK; i += blockDim.x) {
        int e = is64 ? (int)i64[i] : i32[i];
        atomicAdd(&cnt[e], 1);
    }
    __syncthreads();
    if (t == 0) {
        int s = 0;
        for (int e = 0; e < NE; e++) { g_off[e] = s; base[e] = s; s += cnt[e]; }
        g_off[NE] = s;
    }
    __syncthreads();
    for (int i = t; i < TTOK; i += blockDim.x) {
        int e = is64 ? (int)i64[i] : i32[i];
        int p = atomicAdd(&base[e], 1);
        g_perm[p] = i;
    }
}

// ---------------- kernel 2: gate+up GEMM + SwiGLU ----------------
// h[t, n] = silu(x@wg[e])[t,n] * (x@wu[e])[t,n], tokens gathered per expert
__global__ void __launch_bounds__(256)
moe_gateup(const float* __restrict__ x,
           const float* __restrict__ wg,
           const float* __restrict__ wu) {
    extern __shared__ float smem[];
    float* As = smem;                      // 2 * BM*LDA
    float* Bg = smem + 2 * BM * LDA;       // 2 * BK*LDB
    float* Bu = Bg + 2 * BK * LDB;         // 2 * BK*LDB

    const int e   = blockIdx.z;
    const int seg = g_off[e];
    const int cnt = g_off[e + 1] - seg;
    const int m0  = blockIdx.y * BM;
    if (m0 >= cnt) return;
    const int n0 = blockIdx.x * BN;

    const int tid = threadIdx.x;
    const int warp = tid >> 5, lane = tid & 31;
    const int wm = warp >> 1, wn = warp & 1;
    const int qr = lane >> 2, qc = lane & 3;

    const size_t wbase = (size_t)e * DMODEL * DFF + n0;
    const float* wgp = wg + wbase;
    const float* wup = wu + wbase;

    float cg[2][4][4], cu[2][4][4];
    #pragma unroll
    for (int i = 0; i < 2; i++)
        #pragma unroll
        for (int j = 0; j < 4; j++)
            #pragma unroll
            for (int k = 0; k < 4; k++) { cg[i][j][k] = 0.f; cu[i][j][k] = 0.f; }

    auto load_stage = [&](int buf, int k0) {
        float* as = As + buf * BM * LDA;
        float* bg = Bg + buf * BK * LDB;
        float* bu = Bu + buf * BK * LDB;
        #pragma unroll
        for (int i = 0; i < 4; i++) {              // A: 128 rows x 8 chunks
            int id = tid + i * 256;
            int r = id >> 3, c = (id & 7) * 4;
            int gm = m0 + r;
            const float* src = x;
            int sz = 0;
            if (gm < cnt) { src = x + (size_t)g_perm[seg + gm] * DMODEL + k0 + c; sz = 16; }
            cp16(as + r * LDA + c, src, sz);
        }
        #pragma unroll
        for (int i = 0; i < 2; i++) {              // B: 32 rows x 16 chunks, x2 mats
            int id = tid + i * 256;
            int r = id >> 4, c = (id & 15) * 4;
            size_t go = (size_t)(k0 + r) * DFF + c;
            cp16(bg + r * LDB + c, wgp + go, 16);
            cp16(bu + r * LDB + c, wup + go, 16);
        }
        cp_commit();
    };

    load_stage(0, 0);
    const int KT = DMODEL / BK;
    for (int kt = 0; kt < KT; ++kt) {
        if (kt + 1 < KT) {
            load_stage((kt + 1) & 1, (kt + 1) * BK);
            asm volatile("cp.async.wait_group 1;\n");
        } else {
            asm volatile("cp.async.wait_group 0;\n");
        }
        __syncthreads();
        const float* as  = As + (kt & 1) * BM * LDA;
        const float* bgs = Bg + (kt & 1) * BK * LDB;
        const float* bus = Bu + (kt & 1) * BK * LDB;
        #pragma unroll
        for (int ks = 0; ks < BK / 8; ++ks) {
            uint32_t a[2][4], fg[4][2], fu[4][2];
            #pragma unroll
            for (int mt = 0; mt < 2; mt++) {
                int r = wm * 32 + mt * 16 + qr;
                int c = ks * 8 + qc;
                a[mt][0] = f2tf(as[r * LDA + c]);
                a[mt][1] = f2tf(as[(r + 8) * LDA + c]);
                a[mt][2] = f2tf(as[r * LDA + c + 4]);
                a[mt][3] = f2tf(as[(r + 8) * LDA + c + 4]);
            }
            #pragma unroll
            for (int nt = 0; nt < 4; nt++) {
                int cc = wn * 32 + nt * 8 + qr;
                int rr = ks * 8 + qc;
                fg[nt][0] = f2tf(bgs[rr * LDB + cc]);
                fg[nt][1] = f2tf(bgs[(rr + 4) * LDB + cc]);
                fu[nt][0] = f2tf(bus[rr * LDB + cc]);
                fu[nt][1] = f2tf(bus[(rr + 4) * LDB + cc]);
            }
            #pragma unroll
            for (int mt = 0; mt < 2; mt++)
                #pragma unroll
                for (int nt = 0; nt < 4; nt++) {
                    mma8(cg[mt][nt], a[mt], fg[nt]);
                    mma8(cu[mt][nt], a[mt], fu[nt]);
                }
        }
        __syncthreads();
    }

    // epilogue: SwiGLU, write gathered hidden
    #pragma unroll
    for (int mt = 0; mt < 2; mt++)
        #pragma unroll
        for (int nt = 0; nt < 4; nt++)
            #pragma unroll
            for (int i = 0; i < 4; i++) {
                int row = wm * 32 + mt * 16 + qr + ((i >> 1) ? 8 : 0);
                int col = wn * 32 + nt * 8 + qc * 2 + (i & 1);
                int gm = m0 + row;
                if (gm < cnt) {
                    float g = cg[mt][nt][i], u = cu[mt][nt][i];
                    float h = u * (g / (1.f + __expf(-g)));
                    g_h[(size_t)(seg + gm) * DFF + n0 + col] = h;
                }
            }
}

// ---------------- kernel 3: down GEMM, scatter to output ----------------
__global__ void __launch_bounds__(256)
moe_down(const float* __restrict__ wd, float* __restrict__ out) {
    extern __shared__ float smem[];
    float* As = smem;                 // 2 * BM*LDA
    float* Bs = smem + 2 * BM * LDA;  // 2 * BK*LDB

    const int e   = blockIdx.z;
    const int seg = g_off[e];
    const int cnt = g_off[e + 1] - seg;
    const int m0  = blockIdx.y * BM;
    if (m0 >= cnt) return;
    const int n0 = blockIdx.x * BN;

    const int tid = threadIdx.x;
    const int warp = tid >> 5, lane = tid & 31;
    const int wm = warp >> 1, wn = warp & 1;
    const int qr = lane >> 2, qc = lane & 3;

    const float* wdp = wd + (size_t)e * DFF * DMODEL + n0;

    float acc[2][4][4];
    #pragma unroll
    for (int i = 0; i < 2; i++)
        #pragma unroll
        for (int j = 0; j < 4; j++)
            #pragma unroll
            for (int k = 0; k < 4; k++) acc[i][j][k] = 0.f;

    auto load_stage = [&](int buf, int k0) {
        float* as = As + buf * BM * LDA;
        float* bs = Bs + buf * BK * LDB;
        #pragma unroll
        for (int i = 0; i < 4; i++) {
            int id = tid + i * 256;
            int r = id >> 3, c = (id & 7) * 4;
            int gm = m0 + r;
            const float* src = g_h;
            int sz = 0;
            if (gm < cnt) { src = g_h + (size_t)(seg + gm) * DFF + k0 + c; sz = 16; }
            cp16(as + r * LDA + c, src, sz);
        }
        #pragma unroll
        for (int i = 0; i < 2; i++) {
            int id = tid + i * 256;
            int r = id >> 4, c = (id & 15) * 4;
            cp16(bs + r * LDB + c, wdp + (size_t)(k0 + r) * DMODEL + c, 16);
        }
        cp_commit();
    };

    load_stage(0, 0);
    const int KT = DFF / BK;
    for (int kt = 0; kt < KT; ++kt) {
        if (kt + 1 < KT) {
            load_stage((kt + 1) & 1, (kt + 1) * BK);
            asm volatile("cp.async.wait_group 1;\n");
        } else {
            asm volatile("cp.async.wait_group 0;\n");
        }
        __syncthreads();
        const float* as = As + (kt & 1) * BM * LDA;
        const float* bs = Bs + (kt & 1) * BK * LDB;
        #pragma unroll
        for (int ks = 0; ks < BK / 8; ++ks) {
            uint32_t a[2][4], fb[4][2];
            #pragma unroll
            for (int mt = 0; mt < 2; mt++) {
                int r = wm * 32 + mt * 16 + qr;
                int c = ks * 8 + qc;
                a[mt][0] = f2tf(as[r * LDA + c]);
                a[mt][1] = f2tf(as[(r + 8) * LDA + c]);
                a[mt][2] = f2tf(as[r * LDA + c + 4]);
                a[mt][3] = f2tf(as[(r + 8) * LDA + c + 4]);
            }
            #pragma unroll
            for (int nt = 0; nt < 4; nt++) {
                int cc = wn * 32 + nt * 8 + qr;
                int rr = ks * 8 + qc;
                fb[nt][0] = f2tf(bs[rr * LDB + cc]);
                fb[nt][1] = f2tf(bs[(rr + 4) * LDB + cc]);
            }
            #pragma unroll
            for (int mt = 0; mt < 2; mt++)
                #pragma unroll
                for (int nt = 0; nt < 4; nt++)
                    mma8(acc[mt][nt], a[mt], fb[nt]);
        }
        __syncthreads();
    }

    #pragma unroll
    for (int mt = 0; mt < 2; mt++)
        #pragma unroll
        for (int nt = 0; nt < 4; nt++)
            #pragma unroll
            for (int i = 0; i < 4; i++) {
                int row = wm * 32 + mt * 16 + qr + ((i >> 1) ? 8 : 0);
                int col = wn * 32 + nt * 8 + qc * 2 + (i & 1);
                int gm = m0 + row;
                if (gm < cnt)
                    out[(size_t)g_perm[seg + gm] * DMODEL + n0 + col] = acc[mt][nt][i];
            }
}

// ---------------- launch ----------------
extern "C" void kernel_launch(void* const* d_in, const int* in_sizes, int n_in,
                              void* d_out, int out_size) {
    const float* x  = (const float*)d_in[0];
    const void*  ei = d_in[1];
    const float* wg = (const float*)d_in[2];
    const float* wu = (const float*)d_in[3];
    const float* wd = (const float*)d_in[4];
    float* out = (float*)d_out;

    static_assert(2 * (BM * LDA + 2 * BK * LDB) * 4 == 73728, "smem1");
    cudaFuncSetAttribute(moe_gateup, cudaFuncAttributeMaxDynamicSharedMemorySize, 73728);
    cudaFuncSetAttribute(moe_down,   cudaFuncAttributeMaxDynamicSharedMemorySize, 55296);

    moe_build_perm<<<1, 256>>>(ei);

    dim3 g1(DFF / BN, TTOK / BM, NE);       // (64, 16, 8)
    moe_gateup<<<g1, 256, 73728>>>(x, wg, wu);

    dim3 g2(DMODEL / BN, TTOK / BM, NE);    // (16, 16, 8)
    moe_down<<<g2, 256, 55296>>>(wd, out);
}

// round 5
// speedup vs baseline: 1.2390x; 1.2390x over previous
#include <cuda_runtime.h>
#include <cuda_fp16.h>
#include <cstdint>

#define NE 8
#define DMODEL 1024
#define DFF 4096
#define TTOK 2048

// ---------------- scratch ----------------
__device__ int g_perm[TTOK];
__device__ int g_off[NE + 1];
__device__ __align__(16) __half g_x16[(size_t)TTOK * DMODEL];
__device__ __align__(16) __half g_h[(size_t)TTOK * DFF];

// ---------------- helpers ----------------
__device__ __forceinline__ uint32_t s2u(const void* p) {
    return (uint32_t)__cvta_generic_to_shared(p);
}
__device__ __forceinline__ void cpa(uint32_t d, const void* s, int sz) {
    asm volatile("cp.async.cg.shared.global [%0], [%1], 16, %2;" :: "r"(d), "l"(s), "r"(sz));
}
__device__ __forceinline__ void cp_commit() {
    asm volatile("cp.async.commit_group;");
}
__device__ __forceinline__ void cp_wait3() {
    asm volatile("cp.async.wait_group 3;");
}
__device__ __forceinline__ void ldsm4(uint32_t* r, uint32_t a) {
    asm volatile("ldmatrix.sync.aligned.m8n8.x4.shared.b16 {%0,%1,%2,%3}, [%4];"
                 : "=r"(r[0]), "=r"(r[1]), "=r"(r[2]), "=r"(r[3]) : "r"(a));
}
__device__ __forceinline__ void ldsm4t(uint32_t* r, uint32_t a) {
    asm volatile("ldmatrix.sync.aligned.m8n8.x4.trans.shared.b16 {%0,%1,%2,%3}, [%4];"
                 : "=r"(r[0]), "=r"(r[1]), "=r"(r[2]), "=r"(r[3]) : "r"(a));
}
__device__ __forceinline__ void mma16(float* c, const uint32_t* a, uint32_t b0, uint32_t b1) {
    asm volatile("mma.sync.aligned.m16n8k16.row.col.f32.f16.f16.f32 "
                 "{%0,%1,%2,%3},{%4,%5,%6,%7},{%8,%9},{%0,%1,%2,%3};"
                 : "+f"(c[0]), "+f"(c[1]), "+f"(c[2]), "+f"(c[3])
                 : "r"(a[0]), "r"(a[1]), "r"(a[2]), "r"(a[3]), "r"(b0), "r"(b1));
}

// ---------------- kernel 1: bucket tokens by expert ----------------
__global__ void moe_build_perm(const void* eidx_raw) {
    __shared__ int cnt[NE], base[NE], nz;
    int t = threadIdx.x;
    if (t < NE) cnt[t] = 0;
    if (t == 0) nz = 0;
    __syncthreads();
    const int* i32 = (const int*)eidx_raw;
    for (int i = t; i < TTOK / 2; i += blockDim.x)
        if (i32[2 * i + 1] != 0) atomicOr(&nz, 1);
    __syncthreads();
    bool is64 = (nz == 0);
    const long long* i64 = (const long long*)eidx_raw;
    for (int i = t; i < TTOK; i += blockDim.x)
        atomicAdd(&cnt[is64 ? (int)i64[i] : i32[i]], 1);
    __syncthreads();
    if (t == 0) {
        int s = 0;
        for (int e = 0; e < NE; e++) { g_off[e] = s; base[e] = s; s += cnt[e]; }
        g_off[NE] = s;
    }
    __syncthreads();
    for (int i = t; i < TTOK; i += blockDim.x) {
        int e = is64 ? (int)i64[i] : i32[i];
        g_perm[atomicAdd(&base[e], 1)] = i;
    }
}

// ---------------- kernel 2: gather + fp16 convert ----------------
__global__ void moe_gather(const float* __restrict__ x) {
    int src = g_perm[blockIdx.x];
    float4 v = ((const float4*)(x + (size_t)src * DMODEL))[threadIdx.x];
    __half2* d = (__half2*)(g_x16 + (size_t)blockIdx.x * DMODEL + threadIdx.x * 4);
    d[0] = __floats2half2_rn(v.x, v.y);
    d[1] = __floats2half2_rn(v.z, v.w);
}

// SMEM layout gemm1 (bytes):
//   A16  : 4 stages x 128 rows x 40 halfs x 2 = 40960       @ 0
//   BG32 : 4 stages x 32x64 fp32 = 32768                    @ 40960
//   BU32 : 32768                                            @ 73728
//   BG16 : 2 bufs x 32 rows x 72 halfs x 2 = 9216           @ 106496
//   BU16 : 9216                                             @ 115712   total 124928
#define G1_A    0
#define G1_BG32 40960
#define G1_BU32 73728
#define G1_BG16 106496
#define G1_BU16 115712
#define G1_SMEM 124928

// ---------------- kernel 3: gate+up GEMM + SwiGLU ----------------
__global__ void __launch_bounds__(256, 1)
moe_gateup(const float* __restrict__ wg, const float* __restrict__ wu) {
    extern __shared__ char smem[];
    const int e = blockIdx.z, seg = g_off[e], cnt = g_off[e + 1] - seg;
    const int mtile = blockIdx.y;
    if (mtile * 128 >= cnt) return;
    const int m0g = seg + mtile * 128, n0 = blockIdx.x * 64;

    const int tid = threadIdx.x, warp = tid >> 5, lane = tid & 31;
    const int wm = warp >> 1, wn = warp & 1;
    const uint32_t sb = s2u(smem);

    const float* wgp = wg + (size_t)e * DMODEL * DFF + n0;
    const float* wup = wu + (size_t)e * DMODEL * DFF + n0;

    auto issue = [&](int s) {
        int b = s & 3, k0 = s * 32;
        #pragma unroll
        for (int i = 0; i < 2; i++) {           // A: 512 x 16B chunks
            int id = tid + i * 256;
            int r = id >> 2, c = id & 3;
            int gm = mtile * 128 + r;
            cpa(sb + G1_A + b * 10240 + r * 80 + c * 16,
                g_x16 + (size_t)(m0g + r) * DMODEL + k0 + c * 8,
                gm < cnt ? 16 : 0);
        }
        #pragma unroll
        for (int i = 0; i < 2; i++) {           // B: 512 chunks each matrix
            int id = tid + i * 256;
            int r = id >> 4, c = id & 15;
            size_t off = (size_t)(k0 + r) * DFF + c * 4;
            cpa(sb + G1_BG32 + b * 8192 + r * 256 + c * 16, wgp + off, 16);
            cpa(sb + G1_BU32 + b * 8192 + r * 256 + c * 16, wup + off, 16);
        }
        cp_commit();
    };

    for (int s = 0; s < 4; s++) issue(s);

    float cg[2][4][4] = {}, cu[2][4][4] = {};
    const int KT = DMODEL / 32;                 // 32 stages
    for (int s = 0; s < KT; s++) {
        int b3 = s & 3, b1 = s & 1;
        cp_wait3();
        __syncthreads();
        // convert weights fp32 SMEM -> fp16 SMEM (padded stride 72 halfs)
        {
            const float4* pg = (const float4*)(smem + G1_BG32 + b3 * 8192);
            const float4* pu = (const float4*)(smem + G1_BU32 + b3 * 8192);
            #pragma unroll
            for (int i = 0; i < 2; i++) {
                int id = tid + i * 256;
                int r = id >> 4, c = id & 15;
                float4 vg = pg[id], vu = pu[id];
                __half2* dg = (__half2*)(smem + G1_BG16 + b1 * 4608 + r * 144 + c * 8);
                __half2* du = (__half2*)(smem + G1_BU16 + b1 * 4608 + r * 144 + c * 8);
                dg[0] = __floats2half2_rn(vg.x, vg.y);
                dg[1] = __floats2half2_rn(vg.z, vg.w);
                du[0] = __floats2half2_rn(vu.x, vu.y);
                du[1] = __floats2half2_rn(vu.z, vu.w);
            }
        }
        __syncthreads();
        uint32_t sA = sb + G1_A + b3 * 10240;
        uint32_t sG = sb + G1_BG16 + b1 * 4608;
        uint32_t sU = sb + G1_BU16 + b1 * 4608;
        #pragma unroll
        for (int ks = 0; ks < 2; ks++) {
            uint32_t a[2][4], bg[8], bu[8];
            #pragma unroll
            for (int mt = 0; mt < 2; mt++) {
                int row = wm * 32 + mt * 16 + (lane & 15);
                int col = ks * 16 + (lane >> 4) * 8;
                ldsm4(a[mt], sA + row * 80 + col * 2);
            }
            #pragma unroll
            for (int h = 0; h < 2; h++) {
                int kr = ks * 16 + (lane & 15);
                int nc = wn * 32 + h * 16 + (lane >> 4) * 8;
                ldsm4t(&bg[h * 4], sG + kr * 144 + nc * 2);
                ldsm4t(&bu[h * 4], sU + kr * 144 + nc * 2);
            }
            #pragma unroll
            for (int mt = 0; mt < 2; mt++)
                #pragma unroll
                for (int nt = 0; nt < 4; nt++) {
                    mma16(cg[mt][nt], a[mt], bg[nt * 2], bg[nt * 2 + 1]);
                    mma16(cu[mt][nt], a[mt], bu[nt * 2], bu[nt * 2 + 1]);
                }
        }
        __syncthreads();
        if (s + 4 < KT) issue(s + 4);
        else cp_commit();                       // keep group count invariant
    }

    // epilogue: SwiGLU -> fp16 g_h
    const int quad = lane >> 2, tq = lane & 3;
    const int rowsb = cnt - mtile * 128;
    #pragma unroll
    for (int mt = 0; mt < 2; mt++)
        #pragma unroll
        for (int nt = 0; nt < 4; nt++)
            #pragma unroll
            for (int hr = 0; hr < 2; hr++) {
                int row = wm * 32 + mt * 16 + quad + hr * 8;
                if (row < rowsb) {
                    int c = wn * 32 + nt * 8 + tq * 2;
                    float ga = cg[mt][nt][hr * 2], gb = cg[mt][nt][hr * 2 + 1];
                    float ua = cu[mt][nt][hr * 2], ub = cu[mt][nt][hr * 2 + 1];
                    float ha = ua * (ga / (1.f + __expf(-ga)));
                    float hb = ub * (gb / (1.f + __expf(-gb)));
                    *(__half2*)(g_h + (size_t)(m0g + row) * DFF + n0 + c) =
                        __floats2half2_rn(ha, hb);
                }
            }
}

// SMEM layout gemm2: A16 40960 @0; B32 32768 @40960; B16 9216 @73728; total 82944
#define G2_A   0
#define G2_B32 40960
#define G2_B16 73728
#define G2_SMEM 82944

// ---------------- kernel 4: down GEMM, scatter ----------------
__global__ void __launch_bounds__(256, 1)
moe_down(const float* __restrict__ wd, float* __restrict__ out) {
    extern __shared__ char smem[];
    const int e = blockIdx.z, seg = g_off[e], cnt = g_off[e + 1] - seg;
    const int mtile = blockIdx.y;
    if (mtile * 128 >= cnt) return;
    const int m0g = seg + mtile * 128, n0 = blockIdx.x * 64;

    const int tid = threadIdx.x, warp = tid >> 5, lane = tid & 31;
    const int wm = warp >> 1, wn = warp & 1;
    const uint32_t sb = s2u(smem);

    const float* wdp = wd + (size_t)e * DFF * DMODEL + n0;

    auto issue = [&](int s) {
        int b = s & 3, k0 = s * 32;
        #pragma unroll
        for (int i = 0; i < 2; i++) {
            int id = tid + i * 256;
            int r = id >> 2, c = id & 3;
            int gm = mtile * 128 + r;
            cpa(sb + G2_A + b * 10240 + r * 80 + c * 16,
                g_h + (size_t)(m0g + r) * DFF + k0 + c * 8,
                gm < cnt ? 16 : 0);
        }
        #pragma unroll
        for (int i = 0; i < 2; i++) {
            int id = tid + i * 256;
            int r = id >> 4, c = id & 15;
            cpa(sb + G2_B32 + b * 8192 + r * 256 + c * 16,
                wdp + (size_t)(k0 + r) * DMODEL + c * 4, 16);
        }
        cp_commit();
    };

    for (int s = 0; s < 4; s++) issue(s);

    float acc[2][4][4] = {};
    const int KT = DFF / 32;                    // 128 stages
    for (int s = 0; s < KT; s++) {
        int b3 = s & 3, b1 = s & 1;
        cp_wait3();
        __syncthreads();
        {
            const float4* pb = (const float4*)(smem + G2_B32 + b3 * 8192);
            #pragma unroll
            for (int i = 0; i < 2; i++) {
                int id = tid + i * 256;
                int r = id >> 4, c = id & 15;
                float4 v = pb[id];
                __half2* db = (__half2*)(smem + G2_B16 + b1 * 4608 + r * 144 + c * 8);
                db[0] = __floats2half2_rn(v.x, v.y);
                db[1] = __floats2half2_rn(v.z, v.w);
            }
        }
        __syncthreads();
        uint32_t sA = sb + G2_A + b3 * 10240;
        uint32_t sB = sb + G2_B16 + b1 * 4608;
        #pragma unroll
        for (int ks = 0; ks < 2; ks++) {
            uint32_t a[2][4], bb[8];
            #pragma unroll
            for (int mt = 0; mt < 2; mt++) {
                int row = wm * 32 + mt * 16 + (lane & 15);
                int col = ks * 16 + (lane >> 4) * 8;
                ldsm4(a[mt], sA + row * 80 + col * 2);
            }
            #pragma unroll
            for (int h = 0; h < 2; h++) {
                int kr = ks * 16 + (lane & 15);
                int nc = wn * 32 + h * 16 + (lane >> 4) * 8;
                ldsm4t(&bb[h * 4], sB + kr * 144 + nc * 2);
            }
            #pragma unroll
            for (int mt = 0; mt < 2; mt++)
                #pragma unroll
                for (int nt = 0; nt < 4; nt++)
                    mma16(acc[mt][nt], a[mt], bb[nt * 2], bb[nt * 2 + 1]);
        }
        __syncthreads();
        if (s + 4 < KT) issue(s + 4);
        else cp_commit();
    }

    const int quad = lane >> 2, tq = lane & 3;
    const int rowsb = cnt - mtile * 128;
    #pragma unroll
    for (int mt = 0; mt < 2; mt++)
        #pragma unroll
        for (int nt = 0; nt < 4; nt++)
            #pragma unroll
            for (int hr = 0; hr < 2; hr++) {
                int row = wm * 32 + mt * 16 + quad + hr * 8;
                if (row < rowsb) {
                    int c = wn * 32 + nt * 8 + tq * 2;
                    float2 v = make_float2(acc[mt][nt][hr * 2], acc[mt][nt][hr * 2 + 1]);
                    *(float2*)(out + (size_t)g_perm[m0g + row] * DMODEL + n0 + c) = v;
                }
            }
}

// ---------------- launch ----------------
extern "C" void kernel_launch(void* const* d_in, const int* in_sizes, int n_in,
                              void* d_out, int out_size) {
    const float* x  = (const float*)d_in[0];
    const void*  ei = d_in[1];
    const float* wg = (const float*)d_in[2];
    const float* wu = (const float*)d_in[3];
    const float* wd = (const float*)d_in[4];
    float* out = (float*)d_out;

    cudaFuncSetAttribute(moe_gateup, cudaFuncAttributeMaxDynamicSharedMemorySize, G1_SMEM);
    cudaFuncSetAttribute(moe_down,   cudaFuncAttributeMaxDynamicSharedMemorySize, G2_SMEM);

    moe_build_perm<<<1, 256>>>(ei);
    moe_gather<<<TTOK, 256>>>(x);
    moe_gateup<<<dim3(DFF / 64, TTOK / 128, NE), 256, G1_SMEM>>>(wg, wu);
    moe_down  <<<dim3(DMODEL / 64, TTOK / 128, NE), 256, G2_SMEM>>>(wd, out);
}

// round 6
// speedup vs baseline: 1.5504x; 1.2513x over previous
#include <cuda_runtime.h>
#include <cuda_fp16.h>
#include <cstdint>

#define NE 8
#define DMODEL 1024
#define DFF 4096
#define TTOK 2048

// ---------------- scratch ----------------
__device__ int g_perm[TTOK];
__device__ int g_off[NE + 1];
__device__ __align__(16) __half g_x16[(size_t)TTOK * DMODEL];
__device__ __align__(16) __half g_h[(size_t)TTOK * DFF];

// ---------------- helpers ----------------
__device__ __forceinline__ uint32_t s2u(const void* p) {
    return (uint32_t)__cvta_generic_to_shared(p);
}
__device__ __forceinline__ void cpa(uint32_t d, const void* s, int sz) {
    asm volatile("cp.async.cg.shared.global [%0], [%1], 16, %2;" :: "r"(d), "l"(s), "r"(sz));
}
__device__ __forceinline__ void cp_commit() {
    asm volatile("cp.async.commit_group;");
}
__device__ __forceinline__ void cp_wait1() {
    asm volatile("cp.async.wait_group 1;");
}
__device__ __forceinline__ void ldsm4(uint32_t* r, uint32_t a) {
    asm volatile("ldmatrix.sync.aligned.m8n8.x4.shared.b16 {%0,%1,%2,%3}, [%4];"
                 : "=r"(r[0]), "=r"(r[1]), "=r"(r[2]), "=r"(r[3]) : "r"(a));
}
__device__ __forceinline__ void ldsm4t(uint32_t* r, uint32_t a) {
    asm volatile("ldmatrix.sync.aligned.m8n8.x4.trans.shared.b16 {%0,%1,%2,%3}, [%4];"
                 : "=r"(r[0]), "=r"(r[1]), "=r"(r[2]), "=r"(r[3]) : "r"(a));
}
__device__ __forceinline__ void mma16(float* c, const uint32_t* a, uint32_t b0, uint32_t b1) {
    asm volatile("mma.sync.aligned.m16n8k16.row.col.f32.f16.f16.f32 "
                 "{%0,%1,%2,%3},{%4,%5,%6,%7},{%8,%9},{%0,%1,%2,%3};"
                 : "+f"(c[0]), "+f"(c[1]), "+f"(c[2]), "+f"(c[3])
                 : "r"(a[0]), "r"(a[1]), "r"(a[2]), "r"(a[3]), "r"(b0), "r"(b1));
}
__device__ __forceinline__ void sts_f4h(char* base, int id, float4 v) {
    int r = id >> 4, c = id & 15;
    __half2* d = (__half2*)(base + r * 144 + c * 8);
    d[0] = __floats2half2_rn(v.x, v.y);
    d[1] = __floats2half2_rn(v.z, v.w);
}

// ---------------- kernel 1: bucket tokens by expert ----------------
__global__ void moe_build_perm(const void* eidx_raw) {
    __shared__ int cnt[NE], base[NE], nz;
    int t = threadIdx.x;
    if (t < NE) cnt[t] = 0;
    if (t == 0) nz = 0;
    __syncthreads();
    const int* i32 = (const int*)eidx_raw;
    for (int i = t; i < TTOK / 2; i += blockDim.x)
        if (i32[2 * i + 1] != 0) atomicOr(&nz, 1);
    __syncthreads();
    bool is64 = (nz == 0);
    const long long* i64 = (const long long*)eidx_raw;
    for (int i = t; i < TTOK; i += blockDim.x)
        atomicAdd(&cnt[is64 ? (int)i64[i] : i32[i]], 1);
    __syncthreads();
    if (t == 0) {
        int s = 0;
        for (int e = 0; e < NE; e++) { g_off[e] = s; base[e] = s; s += cnt[e]; }
        g_off[NE] = s;
    }
    __syncthreads();
    for (int i = t; i < TTOK; i += blockDim.x) {
        int e = is64 ? (int)i64[i] : i32[i];
        g_perm[atomicAdd(&base[e], 1)] = i;
    }
}

// ---------------- kernel 2: gather + fp16 convert ----------------
__global__ void moe_gather(const float* __restrict__ x) {
    int src = g_perm[blockIdx.x];
    float4 v = ((const float4*)(x + (size_t)src * DMODEL))[threadIdx.x];
    __half2* d = (__half2*)(g_x16 + (size_t)blockIdx.x * DMODEL + threadIdx.x * 4);
    d[0] = __floats2half2_rn(v.x, v.y);
    d[1] = __floats2half2_rn(v.z, v.w);
}

// SMEM gemm1: A16 3 stages x 128 x 80B = 30720 @0; BG16 2 x 4608 @30720; BU16 2 x 4608 @39936; tot 49152
#define G1_A    0
#define G1_BG16 30720
#define G1_BU16 39936
#define G1_SMEM 49152
// SMEM gemm2: A16 30720 @0; B16 2 x 4608 @30720; tot 39936
#define G2_A   0
#define G2_B16 30720
#define G2_SMEM 39936

// ---------------- kernel 3: gate+up GEMM + SwiGLU ----------------
__global__ void __launch_bounds__(256, 2)
moe_gateup(const float* __restrict__ wg, const float* __restrict__ wu) {
    extern __shared__ char smem[];
    const int e = blockIdx.z, seg = g_off[e], cnt = g_off[e + 1] - seg;
    const int mtile = blockIdx.y;
    if (mtile * 128 >= cnt) return;
    const int m0g = seg + mtile * 128, n0 = blockIdx.x * 64;

    const int tid = threadIdx.x, warp = tid >> 5, lane = tid & 31;
    const int wm = warp >> 1, wn = warp & 1;
    const uint32_t sb = s2u(smem);

    const float* wgp = wg + (size_t)e * DMODEL * DFF + n0;
    const float* wup = wu + (size_t)e * DMODEL * DFF + n0;

    // A stage via cp.async (3-stage ring)
    auto stageA = [&](int s) {
        int slot = s % 3, k0 = s * 32;
        #pragma unroll
        for (int i = 0; i < 2; i++) {
            int id = tid + i * 256;
            int r = id >> 2, c = id & 3;
            bool ok = (mtile * 128 + r) < cnt;
            const __half* src = ok ? g_x16 + (size_t)(m0g + r) * DMODEL + k0 + c * 8 : g_x16;
            cpa(sb + G1_A + slot * 10240 + r * 80 + c * 16, src, ok ? 16 : 0);
        }
        cp_commit();
    };
    // B regs prefetch (weights, fp32 LDG)
    float4 rg[2], ru[2];
    auto ldB = [&](int s) {
        int k0 = s * 32;
        #pragma unroll
        for (int i = 0; i < 2; i++) {
            int id = tid + i * 256;
            int r = id >> 4, c = id & 15;
            size_t off = (size_t)(k0 + r) * DFF + c * 4;
            rg[i] = __ldg((const float4*)(wgp + off));
            ru[i] = __ldg((const float4*)(wup + off));
        }
    };

    ldB(0);
    stageA(0);
    stageA(1);

    float cg[2][4][4] = {}, cu[2][4][4] = {};
    const int KT = DMODEL / 32;
    for (int s = 0; s < KT; s++) {
        const int b1 = s & 1, slot = s % 3;
        // 1. STS B(s) from regs (buf b1; safe: MMA(s-2) done before sync(s-1))
        char* bg16 = smem + G1_BG16 + b1 * 4608;
        char* bu16 = smem + G1_BU16 + b1 * 4608;
        #pragma unroll
        for (int i = 0; i < 2; i++) {
            sts_f4h(bg16, tid + i * 256, rg[i]);
            sts_f4h(bu16, tid + i * 256, ru[i]);
        }
        // 2. wait A(s), barrier
        cp_wait1();
        __syncthreads();
        // 3. prefetch next B into regs (latency hidden under MMA)
        if (s + 1 < KT) ldB(s + 1);
        // 4. issue A(s+2) into slot (s-1)%3 (post-sync: MMA(s-1) reads complete)
        if (s + 2 < KT) stageA(s + 2);
        else cp_commit();
        // 5. MMA
        uint32_t sA = sb + G1_A + slot * 10240;
        uint32_t sG = sb + G1_BG16 + b1 * 4608;
        uint32_t sU = sb + G1_BU16 + b1 * 4608;
        #pragma unroll
        for (int ks = 0; ks < 2; ks++) {
            uint32_t a[2][4], bg[8], bu[8];
            #pragma unroll
            for (int mt = 0; mt < 2; mt++) {
                int row = wm * 32 + mt * 16 + (lane & 15);
                int col = ks * 16 + (lane >> 4) * 8;
                ldsm4(a[mt], sA + row * 80 + col * 2);
            }
            #pragma unroll
            for (int h = 0; h < 2; h++) {
                int kr = ks * 16 + (lane & 15);
                int nc = wn * 32 + h * 16 + (lane >> 4) * 8;
                ldsm4t(&bg[h * 4], sG + kr * 144 + nc * 2);
                ldsm4t(&bu[h * 4], sU + kr * 144 + nc * 2);
            }
            #pragma unroll
            for (int mt = 0; mt < 2; mt++)
                #pragma unroll
                for (int nt = 0; nt < 4; nt++) {
                    mma16(cg[mt][nt], a[mt], bg[nt * 2], bg[nt * 2 + 1]);
                    mma16(cu[mt][nt], a[mt], bu[nt * 2], bu[nt * 2 + 1]);
                }
        }
        __syncthreads();   // protect B16 buf b1 before STS at s+2
    }

    // epilogue: SwiGLU -> fp16 g_h
    const int quad = lane >> 2, tq = lane & 3;
    const int rowsb = cnt - mtile * 128;
    #pragma unroll
    for (int mt = 0; mt < 2; mt++)
        #pragma unroll
        for (int nt = 0; nt < 4; nt++)
            #pragma unroll
            for (int hr = 0; hr < 2; hr++) {
                int row = wm * 32 + mt * 16 + quad + hr * 8;
                if (row < rowsb) {
                    int c = wn * 32 + nt * 8 + tq * 2;
                    float ga = cg[mt][nt][hr * 2], gb = cg[mt][nt][hr * 2 + 1];
                    float ua = cu[mt][nt][hr * 2], ub = cu[mt][nt][hr * 2 + 1];
                    float ha = ua * (ga / (1.f + __expf(-ga)));
                    float hb = ub * (gb / (1.f + __expf(-gb)));
                    *(__half2*)(g_h + (size_t)(m0g + row) * DFF + n0 + c) =
                        __floats2half2_rn(ha, hb);
                }
            }
}

// ---------------- kernel 4: down GEMM, scatter ----------------
__global__ void __launch_bounds__(256, 2)
moe_down(const float* __restrict__ wd, float* __restrict__ out) {
    extern __shared__ char smem[];
    const int e = blockIdx.z, seg = g_off[e], cnt = g_off[e + 1] - seg;
    const int mtile = blockIdx.y;
    if (mtile * 128 >= cnt) return;
    const int m0g = seg + mtile * 128, n0 = blockIdx.x * 64;

    const int tid = threadIdx.x, warp = tid >> 5, lane = tid & 31;
    const int wm = warp >> 1, wn = warp & 1;
    const uint32_t sb = s2u(smem);

    const float* wdp = wd + (size_t)e * DFF * DMODEL + n0;

    auto stageA = [&](int s) {
        int slot = s % 3, k0 = s * 32;
        #pragma unroll
        for (int i = 0; i < 2; i++) {
            int id = tid + i * 256;
            int r = id >> 2, c = id & 3;
            bool ok = (mtile * 128 + r) < cnt;
            const __half* src = ok ? g_h + (size_t)(m0g + r) * DFF + k0 + c * 8 : g_h;
            cpa(sb + G2_A + slot * 10240 + r * 80 + c * 16, src, ok ? 16 : 0);
        }
        cp_commit();
    };
    float4 rb[2];
    auto ldB = [&](int s) {
        int k0 = s * 32;
        #pragma unroll
        for (int i = 0; i < 2; i++) {
            int id = tid + i * 256;
            int r = id >> 4, c = id & 15;
            rb[i] = __ldg((const float4*)(wdp + (size_t)(k0 + r) * DMODEL + c * 4));
        }
    };

    ldB(0);
    stageA(0);
    stageA(1);

    float acc[2][4][4] = {};
    const int KT = DFF / 32;
    for (int s = 0; s < KT; s++) {
        const int b1 = s & 1, slot = s % 3;
        char* b16 = smem + G2_B16 + b1 * 4608;
        #pragma unroll
        for (int i = 0; i < 2; i++)
            sts_f4h(b16, tid + i * 256, rb[i]);
        cp_wait1();
        __syncthreads();
        if (s + 1 < KT) ldB(s + 1);
        if (s + 2 < KT) stageA(s + 2);
        else cp_commit();
        uint32_t sA = sb + G2_A + slot * 10240;
        uint32_t sB = sb + G2_B16 + b1 * 4608;
        #pragma unroll
        for (int ks = 0; ks < 2; ks++) {
            uint32_t a[2][4], bb[8];
            #pragma unroll
            for (int mt = 0; mt < 2; mt++) {
                int row = wm * 32 + mt * 16 + (lane & 15);
                int col = ks * 16 + (lane >> 4) * 8;
                ldsm4(a[mt], sA + row * 80 + col * 2);
            }
            #pragma unroll
            for (int h = 0; h < 2; h++) {
                int kr = ks * 16 + (lane & 15);
                int nc = wn * 32 + h * 16 + (lane >> 4) * 8;
                ldsm4t(&bb[h * 4], sB + kr * 144 + nc * 2);
            }
            #pragma unroll
            for (int mt = 0; mt < 2; mt++)
                #pragma unroll
                for (int nt = 0; nt < 4; nt++)
                    mma16(acc[mt][nt], a[mt], bb[nt * 2], bb[nt * 2 + 1]);
        }
        __syncthreads();
    }

    const int quad = lane >> 2, tq = lane & 3;
    const int rowsb = cnt - mtile * 128;
    #pragma unroll
    for (int mt = 0; mt < 2; mt++)
        #pragma unroll
        for (int nt = 0; nt < 4; nt++)
            #pragma unroll
            for (int hr = 0; hr < 2; hr++) {
                int row = wm * 32 + mt * 16 + quad + hr * 8;
                if (row < rowsb) {
                    int c = wn * 32 + nt * 8 + tq * 2;
                    float2 v = make_float2(acc[mt][nt][hr * 2], acc[mt][nt][hr * 2 + 1]);
                    *(float2*)(out + (size_t)g_perm[m0g + row] * DMODEL + n0 + c) = v;
                }
            }
}

// ---------------- launch ----------------
extern "C" void kernel_launch(void* const* d_in, const int* in_sizes, int n_in,
                              void* d_out, int out_size) {
    const float* x  = (const float*)d_in[0];
    const void*  ei = d_in[1];
    const float* wg = (const float*)d_in[2];
    const float* wu = (const float*)d_in[3];
    const float* wd = (const float*)d_in[4];
    float* out = (float*)d_out;

    cudaFuncSetAttribute(moe_gateup, cudaFuncAttributeMaxDynamicSharedMemorySize, G1_SMEM);
    cudaFuncSetAttribute(moe_down,   cudaFuncAttributeMaxDynamicSharedMemorySize, G2_SMEM);

    moe_build_perm<<<1, 256>>>(ei);
    moe_gather<<<TTOK, 256>>>(x);
    moe_gateup<<<dim3(DFF / 64, TTOK / 128, NE), 256, G1_SMEM>>>(wg, wu);
    moe_down  <<<dim3(DMODEL / 64, TTOK / 128, NE), 256, G2_SMEM>>>(wd, out);
}

// round 7
// speedup vs baseline: 1.7629x; 1.1371x over previous
#include <cuda_runtime.h>
#include <cuda_fp16.h>
#include <cstdint>

#define NE 8
#define DMODEL 1024
#define DFF 4096
#define TTOK 2048
#define NSPLIT 4

// ---------------- scratch ----------------
__device__ int g_perm[TTOK];
__device__ int g_off[NE + 1];
__device__ __align__(16) __half g_x16[(size_t)TTOK * DMODEL];
__device__ __align__(16) __half g_h[(size_t)TTOK * DFF];
__device__ __align__(16) float g_part[NSPLIT][TTOK][DMODEL];

// ---------------- helpers ----------------
__device__ __forceinline__ uint32_t s2u(const void* p) {
    return (uint32_t)__cvta_generic_to_shared(p);
}
__device__ __forceinline__ void cpa(uint32_t d, const void* s, int sz) {
    asm volatile("cp.async.cg.shared.global [%0], [%1], 16, %2;" :: "r"(d), "l"(s), "r"(sz));
}
__device__ __forceinline__ void cp_commit() {
    asm volatile("cp.async.commit_group;");
}
__device__ __forceinline__ void cp_wait1() {
    asm volatile("cp.async.wait_group 1;");
}
__device__ __forceinline__ void ldsm4(uint32_t* r, uint32_t a) {
    asm volatile("ldmatrix.sync.aligned.m8n8.x4.shared.b16 {%0,%1,%2,%3}, [%4];"
                 : "=r"(r[0]), "=r"(r[1]), "=r"(r[2]), "=r"(r[3]) : "r"(a));
}
__device__ __forceinline__ void ldsm4t(uint32_t* r, uint32_t a) {
    asm volatile("ldmatrix.sync.aligned.m8n8.x4.trans.shared.b16 {%0,%1,%2,%3}, [%4];"
                 : "=r"(r[0]), "=r"(r[1]), "=r"(r[2]), "=r"(r[3]) : "r"(a));
}
__device__ __forceinline__ void mma16(float* c, const uint32_t* a, uint32_t b0, uint32_t b1) {
    asm volatile("mma.sync.aligned.m16n8k16.row.col.f32.f16.f16.f32 "
                 "{%0,%1,%2,%3},{%4,%5,%6,%7},{%8,%9},{%0,%1,%2,%3};"
                 : "+f"(c[0]), "+f"(c[1]), "+f"(c[2]), "+f"(c[3])
                 : "r"(a[0]), "r"(a[1]), "r"(a[2]), "r"(a[3]), "r"(b0), "r"(b1));
}
__device__ __forceinline__ void sts_f4h(char* base, int id, float4 v) {
    int r = id >> 4, c = id & 15;
    __half2* d = (__half2*)(base + r * 144 + c * 8);
    d[0] = __floats2half2_rn(v.x, v.y);
    d[1] = __floats2half2_rn(v.z, v.w);
}

// ---------------- kernel 1: bucket tokens by expert ----------------
__global__ void moe_build_perm(const void* eidx_raw) {
    __shared__ int cnt[NE], base[NE], nz;
    int t = threadIdx.x;
    if (t < NE) cnt[t] = 0;
    if (t == 0) nz = 0;
    __syncthreads();
    const int* i32 = (const int*)eidx_raw;
    for (int i = t; i < TTOK / 2; i += blockDim.x)
        if (i32[2 * i + 1] != 0) atomicOr(&nz, 1);
    __syncthreads();
    bool is64 = (nz == 0);
    const long long* i64 = (const long long*)eidx_raw;
    for (int i = t; i < TTOK; i += blockDim.x)
        atomicAdd(&cnt[is64 ? (int)i64[i] : i32[i]], 1);
    __syncthreads();
    if (t == 0) {
        int s = 0;
        for (int e = 0; e < NE; e++) { g_off[e] = s; base[e] = s; s += cnt[e]; }
        g_off[NE] = s;
    }
    __syncthreads();
    for (int i = t; i < TTOK; i += blockDim.x) {
        int e = is64 ? (int)i64[i] : i32[i];
        g_perm[atomicAdd(&base[e], 1)] = i;
    }
}

// ---------------- kernel 2: gather + fp16 convert ----------------
__global__ void moe_gather(const float* __restrict__ x) {
    int src = g_perm[blockIdx.x];
    float4 v = ((const float4*)(x + (size_t)src * DMODEL))[threadIdx.x];
    __half2* d = (__half2*)(g_x16 + (size_t)blockIdx.x * DMODEL + threadIdx.x * 4);
    d[0] = __floats2half2_rn(v.x, v.y);
    d[1] = __floats2half2_rn(v.z, v.w);
}

// SMEM gemm1: A16 3 stages x 128 x 80B = 30720 @0; BG16 2 x 4608; BU16 2 x 4608; tot 49152
#define G1_A    0
#define G1_BG16 30720
#define G1_BU16 39936
#define G1_SMEM 49152
// SMEM gemm2: A16 30720 @0; B16 2 x 4608 @30720; tot 39936
#define G2_A   0
#define G2_B16 30720
#define G2_SMEM 39936

// ---------------- kernel 3: gate+up GEMM + SwiGLU ----------------
__global__ void __launch_bounds__(256, 2)
moe_gateup(const float* __restrict__ wg, const float* __restrict__ wu) {
    extern __shared__ char smem[];
    const int e = blockIdx.z, seg = g_off[e], cnt = g_off[e + 1] - seg;
    const int mtile = blockIdx.y;
    if (mtile * 128 >= cnt) return;
    const int m0g = seg + mtile * 128, n0 = blockIdx.x * 64;

    const int tid = threadIdx.x, warp = tid >> 5, lane = tid & 31;
    const int wm = warp >> 1, wn = warp & 1;
    const uint32_t sb = s2u(smem);

    const float* wgp = wg + (size_t)e * DMODEL * DFF + n0;
    const float* wup = wu + (size_t)e * DMODEL * DFF + n0;

    auto stageA = [&](int s) {
        int slot = s % 3, k0 = s * 32;
        #pragma unroll
        for (int i = 0; i < 2; i++) {
            int id = tid + i * 256;
            int r = id >> 2, c = id & 3;
            bool ok = (mtile * 128 + r) < cnt;
            const __half* src = ok ? g_x16 + (size_t)(m0g + r) * DMODEL + k0 + c * 8 : g_x16;
            cpa(sb + G1_A + slot * 10240 + r * 80 + c * 16, src, ok ? 16 : 0);
        }
        cp_commit();
    };
    float4 rg[2], ru[2];
    auto ldB = [&](int s) {
        int k0 = s * 32;
        #pragma unroll
        for (int i = 0; i < 2; i++) {
            int id = tid + i * 256;
            int r = id >> 4, c = id & 15;
            size_t off = (size_t)(k0 + r) * DFF + c * 4;
            rg[i] = __ldg((const float4*)(wgp + off));
            ru[i] = __ldg((const float4*)(wup + off));
        }
    };

    ldB(0);
    stageA(0);
    stageA(1);

    float cg[2][4][4] = {}, cu[2][4][4] = {};
    const int KT = DMODEL / 32;
    for (int s = 0; s < KT; s++) {
        const int b1 = s & 1, slot = s % 3;
        char* bg16 = smem + G1_BG16 + b1 * 4608;
        char* bu16 = smem + G1_BU16 + b1 * 4608;
        #pragma unroll
        for (int i = 0; i < 2; i++) {
            sts_f4h(bg16, tid + i * 256, rg[i]);
            sts_f4h(bu16, tid + i * 256, ru[i]);
        }
        cp_wait1();
        __syncthreads();
        if (s + 1 < KT) ldB(s + 1);
        if (s + 2 < KT) stageA(s + 2);
        else cp_commit();
        uint32_t sA = sb + G1_A + slot * 10240;
        uint32_t sG = sb + G1_BG16 + b1 * 4608;
        uint32_t sU = sb + G1_BU16 + b1 * 4608;
        #pragma unroll
        for (int ks = 0; ks < 2; ks++) {
            uint32_t a[2][4], bg[8], bu[8];
            #pragma unroll
            for (int mt = 0; mt < 2; mt++) {
                int row = wm * 32 + mt * 16 + (lane & 15);
                int col = ks * 16 + (lane >> 4) * 8;
                ldsm4(a[mt], sA + row * 80 + col * 2);
            }
            #pragma unroll
            for (int h = 0; h < 2; h++) {
                int kr = ks * 16 + (lane & 15);
                int nc = wn * 32 + h * 16 + (lane >> 4) * 8;
                ldsm4t(&bg[h * 4], sG + kr * 144 + nc * 2);
                ldsm4t(&bu[h * 4], sU + kr * 144 + nc * 2);
            }
            #pragma unroll
            for (int mt = 0; mt < 2; mt++)
                #pragma unroll
                for (int nt = 0; nt < 4; nt++) {
                    mma16(cg[mt][nt], a[mt], bg[nt * 2], bg[nt * 2 + 1]);
                    mma16(cu[mt][nt], a[mt], bu[nt * 2], bu[nt * 2 + 1]);
                }
        }
        // no trailing sync: next stage's STS targets the other B buf, and the
        // mid-stage sync orders MMA(s) reads before STS(s+2) overwrites.
    }

    const int quad = lane >> 2, tq = lane & 3;
    const int rowsb = cnt - mtile * 128;
    #pragma unroll
    for (int mt = 0; mt < 2; mt++)
        #pragma unroll
        for (int nt = 0; nt < 4; nt++)
            #pragma unroll
            for (int hr = 0; hr < 2; hr++) {
                int row = wm * 32 + mt * 16 + quad + hr * 8;
                if (row < rowsb) {
                    int c = wn * 32 + nt * 8 + tq * 2;
                    float ga = cg[mt][nt][hr * 2], gb = cg[mt][nt][hr * 2 + 1];
                    float ua = cu[mt][nt][hr * 2], ub = cu[mt][nt][hr * 2 + 1];
                    float ha = ua * (ga / (1.f + __expf(-ga)));
                    float hb = ub * (gb / (1.f + __expf(-gb)));
                    *(__half2*)(g_h + (size_t)(m0g + row) * DFF + n0 + c) =
                        __floats2half2_rn(ha, hb);
                }
            }
}

// ---------------- kernel 4: down GEMM split-K partials ----------------
__global__ void __launch_bounds__(256, 2)
moe_down_part(const float* __restrict__ wd) {
    extern __shared__ char smem[];
    const int split = blockIdx.z & (NSPLIT - 1), e = blockIdx.z / NSPLIT;
    const int seg = g_off[e], cnt = g_off[e + 1] - seg;
    const int mtile = blockIdx.y;
    if (mtile * 128 >= cnt) return;
    const int m0g = seg + mtile * 128, n0 = blockIdx.x * 64;
    const int kbase = split * (DFF / NSPLIT);

    const int tid = threadIdx.x, warp = tid >> 5, lane = tid & 31;
    const int wm = warp >> 1, wn = warp & 1;
    const uint32_t sb = s2u(smem);

    const float* wdp = wd + (size_t)e * DFF * DMODEL + n0;

    auto stageA = [&](int s) {
        int slot = s % 3, k0 = kbase + s * 32;
        #pragma unroll
        for (int i = 0; i < 2; i++) {
            int id = tid + i * 256;
            int r = id >> 2, c = id & 3;
            bool ok = (mtile * 128 + r) < cnt;
            const __half* src = ok ? g_h + (size_t)(m0g + r) * DFF + k0 + c * 8 : g_h;
            cpa(sb + G2_A + slot * 10240 + r * 80 + c * 16, src, ok ? 16 : 0);
        }
        cp_commit();
    };
    float4 rb[2];
    auto ldB = [&](int s) {
        int k0 = kbase + s * 32;
        #pragma unroll
        for (int i = 0; i < 2; i++) {
            int id = tid + i * 256;
            int r = id >> 4, c = id & 15;
            rb[i] = __ldg((const float4*)(wdp + (size_t)(k0 + r) * DMODEL + c * 4));
        }
    };

    ldB(0);
    stageA(0);
    stageA(1);

    float acc[2][4][4] = {};
    const int KT = (DFF / NSPLIT) / 32;   // 32 stages
    for (int s = 0; s < KT; s++) {
        const int b1 = s & 1, slot = s % 3;
        char* b16 = smem + G2_B16 + b1 * 4608;
        #pragma unroll
        for (int i = 0; i < 2; i++)
            sts_f4h(b16, tid + i * 256, rb[i]);
        cp_wait1();
        __syncthreads();
        if (s + 1 < KT) ldB(s + 1);
        if (s + 2 < KT) stageA(s + 2);
        else cp_commit();
        uint32_t sA = sb + G2_A + slot * 10240;
        uint32_t sB = sb + G2_B16 + b1 * 4608;
        #pragma unroll
        for (int ks = 0; ks < 2; ks++) {
            uint32_t a[2][4], bb[8];
            #pragma unroll
            for (int mt = 0; mt < 2; mt++) {
                int row = wm * 32 + mt * 16 + (lane & 15);
                int col = ks * 16 + (lane >> 4) * 8;
                ldsm4(a[mt], sA + row * 80 + col * 2);
            }
            #pragma unroll
            for (int h = 0; h < 2; h++) {
                int kr = ks * 16 + (lane & 15);
                int nc = wn * 32 + h * 16 + (lane >> 4) * 8;
                ldsm4t(&bb[h * 4], sB + kr * 144 + nc * 2);
            }
            #pragma unroll
            for (int mt = 0; mt < 2; mt++)
                #pragma unroll
                for (int nt = 0; nt < 4; nt++)
                    mma16(acc[mt][nt], a[mt], bb[nt * 2], bb[nt * 2 + 1]);
        }
    }

    const int quad = lane >> 2, tq = lane & 3;
    const int rowsb = cnt - mtile * 128;
    #pragma unroll
    for (int mt = 0; mt < 2; mt++)
        #pragma unroll
        for (int nt = 0; nt < 4; nt++)
            #pragma unroll
            for (int hr = 0; hr < 2; hr++) {
                int row = wm * 32 + mt * 16 + quad + hr * 8;
                if (row < rowsb) {
                    int c = wn * 32 + nt * 8 + tq * 2;
                    float2 v = make_float2(acc[mt][nt][hr * 2], acc[mt][nt][hr * 2 + 1]);
                    *(float2*)(&g_part[split][m0g + row][n0 + c]) = v;
                }
            }
}

// ---------------- kernel 5: reduce partials + scatter ----------------
__global__ void moe_reduce(float* __restrict__ out) {
    int t = blockIdx.x, d = threadIdx.x * 4;
    float4 a = *(const float4*)(&g_part[0][t][d]);
    float4 b = *(const float4*)(&g_part[1][t][d]);
    float4 c = *(const float4*)(&g_part[2][t][d]);
    float4 e = *(const float4*)(&g_part[3][t][d]);
    float4 r;
    r.x = (a.x + b.x) + (c.x + e.x);
    r.y = (a.y + b.y) + (c.y + e.y);
    r.z = (a.z + b.z) + (c.z + e.z);
    r.w = (a.w + b.w) + (c.w + e.w);
    *(float4*)(out + (size_t)g_perm[t] * DMODEL + d) = r;
}

// ---------------- launch ----------------
extern "C" void kernel_launch(void* const* d_in, const int* in_sizes, int n_in,
                              void* d_out, int out_size) {
    const float* x  = (const float*)d_in[0];
    const void*  ei = d_in[1];
    const float* wg = (const float*)d_in[2];
    const float* wu = (const float*)d_in[3];
    const float* wd = (const float*)d_in[4];
    float* out = (float*)d_out;

    cudaFuncSetAttribute(moe_gateup, cudaFuncAttributeMaxDynamicSharedMemorySize, G1_SMEM);
    cudaFuncSetAttribute(moe_down_part, cudaFuncAttributeMaxDynamicSharedMemorySize, G2_SMEM);

    moe_build_perm<<<1, 256>>>(ei);
    moe_gather<<<TTOK, 256>>>(x);
    moe_gateup<<<dim3(DFF / 64, TTOK / 128, NE), 256, G1_SMEM>>>(wg, wu);
    moe_down_part<<<dim3(DMODEL / 64, TTOK / 128, NE * NSPLIT), 256, G2_SMEM>>>(wd);
    moe_reduce<<<TTOK, 256>>>(out);
}